// round 1
// baseline (speedup 1.0000x reference)
#include <cuda_runtime.h>
#include <math.h>

#define Bn   128
#define Tn   256
#define Cn   384
#define Hn   6
#define Dn   64
#define NQKV 1152
#define Mrows (Bn*Tn)   // 32768

// Scratch (device globals: allocation-free by rule)
__device__ float g_Q[(size_t)Bn*Hn*Tn*Dn];
__device__ float g_K[(size_t)Bn*Hn*Tn*Dn];
__device__ float g_V[(size_t)Bn*Hn*Tn*Dn];
__device__ float g_O[(size_t)Bn*Hn*Tn*Dn];

// ---------------------------------------------------------------------------
// Kernel 1: qkv = x @ W_qkv  (M=32768, N=1152, K=384), fused RoPE on q,k,
// scatter to head-major [B,H,T,D] scratch.
// Tiling: BM=BN=128, BK=16, 256 threads, 8x8 microtile.
// ---------------------------------------------------------------------------
__global__ __launch_bounds__(256) void qkv_rope_kernel(
    const float* __restrict__ x, const float* __restrict__ W)
{
    __shared__ float As[16][128];
    __shared__ float Bs[16][128];

    const int tid     = threadIdx.x;
    const int rowBase = blockIdx.y * 128;
    const int colBase = blockIdx.x * 128;

    float acc[8][8];
    #pragma unroll
    for (int i = 0; i < 8; i++)
        #pragma unroll
        for (int j = 0; j < 8; j++) acc[i][j] = 0.f;

    const int aRow = tid >> 2;          // 0..63
    const int aCol = (tid & 3) * 4;     // 0,4,8,12
    const int bRow = tid >> 5;          // 0..7
    const int bCol = (tid & 31) * 4;    // 0..124
    const int tr = (tid >> 4) * 8;
    const int tc = (tid & 15) * 8;

    for (int k0 = 0; k0 < Cn; k0 += 16) {
        #pragma unroll
        for (int rr = 0; rr < 128; rr += 64) {
            float4 v = *(const float4*)(x + (size_t)(rowBase + aRow + rr) * Cn + k0 + aCol);
            As[aCol + 0][aRow + rr] = v.x;
            As[aCol + 1][aRow + rr] = v.y;
            As[aCol + 2][aRow + rr] = v.z;
            As[aCol + 3][aRow + rr] = v.w;
        }
        #pragma unroll
        for (int rr = 0; rr < 16; rr += 8) {
            *(float4*)(&Bs[bRow + rr][bCol]) =
                *(const float4*)(W + (size_t)(k0 + bRow + rr) * NQKV + colBase + bCol);
        }
        __syncthreads();

        #pragma unroll
        for (int kk = 0; kk < 16; kk++) {
            float a[8], b[8];
            *(float4*)(a)     = *(float4*)(&As[kk][tr]);
            *(float4*)(a + 4) = *(float4*)(&As[kk][tr + 4]);
            *(float4*)(b)     = *(float4*)(&Bs[kk][tc]);
            *(float4*)(b + 4) = *(float4*)(&Bs[kk][tc + 4]);
            #pragma unroll
            for (int i = 0; i < 8; i++)
                #pragma unroll
                for (int j = 0; j < 8; j++)
                    acc[i][j] = fmaf(a[i], b[j], acc[i][j]);
        }
        __syncthreads();
    }

    // Epilogue: RoPE on q,k; scatter to [B,H,T,D]
    #pragma unroll
    for (int i = 0; i < 8; i++) {
        const int gr = rowBase + tr + i;
        const int bb = gr >> 8;
        const int t  = gr & 255;
        #pragma unroll
        for (int jg = 0; jg < 8; jg += 4) {
            const int gc  = colBase + tc + jg;
            const int sel = gc / Cn;           // 0=q 1=k 2=v
            const int rem = gc - sel * Cn;
            const int h   = rem >> 6;
            const int d   = rem & 63;          // multiple of 4

            float v[4] = {acc[i][jg], acc[i][jg+1], acc[i][jg+2], acc[i][jg+3]};
            if (sel < 2) {
                #pragma unroll
                for (int pp = 0; pp < 2; pp++) {
                    const int p = (d >> 1) + pp;
                    // inv_freq = 10000^(-p/32) = exp2(-p * log2(10000)/32)
                    float theta = (float)t * exp2f(-(float)p * 0.41524101186f);
                    float sn, cs;
                    sincosf(theta, &sn, &cs);
                    float a0 = v[2*pp], a1 = v[2*pp + 1];
                    v[2*pp]     = a0 * cs - a1 * sn;
                    v[2*pp + 1] = a1 * cs + a0 * sn;
                }
            }
            float* dst = (sel == 0) ? g_Q : ((sel == 1) ? g_K : g_V);
            size_t idx = ((((size_t)bb * Hn + h) * Tn + t) * Dn) + d;
            *(float4*)(dst + idx) = make_float4(v[0], v[1], v[2], v[3]);
        }
    }
}

// ---------------------------------------------------------------------------
// Kernel 2: causal attention per (b,h). CTA = 256 threads, thread r = query
// row r. K,V fully resident in 128KB dynamic smem. Online softmax.
// ---------------------------------------------------------------------------
__global__ __launch_bounds__(256) void attn_kernel()
{
    extern __shared__ float sh[];
    float* Ks = sh;                 // 256*64
    float* Vs = sh + Tn * Dn;       // 256*64

    const int bh = blockIdx.x;
    const size_t base = (size_t)bh * Tn * Dn;
    const int tid = threadIdx.x;

    const float4* K4 = (const float4*)(g_K + base);
    const float4* V4 = (const float4*)(g_V + base);
    for (int i = tid; i < Tn * Dn / 4; i += 256) {
        ((float4*)Ks)[i] = K4[i];
        ((float4*)Vs)[i] = V4[i];
    }
    __syncthreads();

    const int r = tid;
    float q[64];
    #pragma unroll
    for (int i = 0; i < 16; i++) {
        float4 v = *(const float4*)(g_Q + base + (size_t)r * Dn + i * 4);
        q[i*4 + 0] = v.x * 0.125f;   // scale = 1/sqrt(64)
        q[i*4 + 1] = v.y * 0.125f;
        q[i*4 + 2] = v.z * 0.125f;
        q[i*4 + 3] = v.w * 0.125f;
    }

    float m = -INFINITY, l = 0.f;
    float o[64];
    #pragma unroll
    for (int d = 0; d < 64; d++) o[d] = 0.f;

    const int jend = r | 31;        // warp-uniform causal trim
    for (int j = 0; j <= jend; j++) {
        const float* kr = Ks + j * Dn;
        float s0 = 0.f, s1 = 0.f, s2 = 0.f, s3 = 0.f;
        #pragma unroll
        for (int d = 0; d < 64; d += 4) {
            s0 = fmaf(q[d + 0], kr[d + 0], s0);
            s1 = fmaf(q[d + 1], kr[d + 1], s1);
            s2 = fmaf(q[d + 2], kr[d + 2], s2);
            s3 = fmaf(q[d + 3], kr[d + 3], s3);
        }
        float s = (s0 + s1) + (s2 + s3);
        if (j <= r) {
            float mn   = fmaxf(m, s);
            float corr = __expf(m - mn);     // exp(-inf)=0 on first iter
            float p    = __expf(s - mn);
            l = l * corr + p;
            const float* vr = Vs + j * Dn;
            #pragma unroll
            for (int d = 0; d < 64; d++)
                o[d] = fmaf(o[d], corr, p * vr[d]);
            m = mn;
        }
    }

    const float inv = 1.f / l;
    #pragma unroll
    for (int i = 0; i < 16; i++) {
        float4 v;
        v.x = o[i*4 + 0] * inv;
        v.y = o[i*4 + 1] * inv;
        v.z = o[i*4 + 2] * inv;
        v.w = o[i*4 + 3] * inv;
        *(float4*)(g_O + base + (size_t)r * Dn + i * 4) = v;
    }
}

// ---------------------------------------------------------------------------
// Kernel 3: out = attnO @ W_proj  (M=32768, N=384, K=384).
// A-tile load gathers from head-major g_O (transpose fused).
// ---------------------------------------------------------------------------
__global__ __launch_bounds__(256) void proj_kernel(
    const float* __restrict__ W, float* __restrict__ out)
{
    __shared__ float As[16][128];
    __shared__ float Bs[16][128];

    const int tid     = threadIdx.x;
    const int rowBase = blockIdx.y * 128;
    const int colBase = blockIdx.x * 128;

    float acc[8][8];
    #pragma unroll
    for (int i = 0; i < 8; i++)
        #pragma unroll
        for (int j = 0; j < 8; j++) acc[i][j] = 0.f;

    const int aRow = tid >> 2;
    const int aCol = (tid & 3) * 4;
    const int bRow = tid >> 5;
    const int bCol = (tid & 31) * 4;
    const int tr = (tid >> 4) * 8;
    const int tc = (tid & 15) * 8;

    for (int k0 = 0; k0 < Cn; k0 += 16) {
        #pragma unroll
        for (int rr = 0; rr < 128; rr += 64) {
            const int gr = rowBase + aRow + rr;
            const int bb = gr >> 8;
            const int t  = gr & 255;
            const int kk = k0 + aCol;       // 4-aligned, within one head
            const int h  = kk >> 6;
            const int d  = kk & 63;
            float4 v = *(const float4*)(g_O + ((((size_t)bb * Hn + h) * Tn + t) * Dn) + d);
            As[aCol + 0][aRow + rr] = v.x;
            As[aCol + 1][aRow + rr] = v.y;
            As[aCol + 2][aRow + rr] = v.z;
            As[aCol + 3][aRow + rr] = v.w;
        }
        #pragma unroll
        for (int rr = 0; rr < 16; rr += 8) {
            *(float4*)(&Bs[bRow + rr][bCol]) =
                *(const float4*)(W + (size_t)(k0 + bRow + rr) * Cn + colBase + bCol);
        }
        __syncthreads();

        #pragma unroll
        for (int kk = 0; kk < 16; kk++) {
            float a[8], b[8];
            *(float4*)(a)     = *(float4*)(&As[kk][tr]);
            *(float4*)(a + 4) = *(float4*)(&As[kk][tr + 4]);
            *(float4*)(b)     = *(float4*)(&Bs[kk][tc]);
            *(float4*)(b + 4) = *(float4*)(&Bs[kk][tc + 4]);
            #pragma unroll
            for (int i = 0; i < 8; i++)
                #pragma unroll
                for (int j = 0; j < 8; j++)
                    acc[i][j] = fmaf(a[i], b[j], acc[i][j]);
        }
        __syncthreads();
    }

    #pragma unroll
    for (int i = 0; i < 8; i++) {
        const int gr = rowBase + tr + i;
        #pragma unroll
        for (int jg = 0; jg < 8; jg += 4) {
            *(float4*)(out + (size_t)gr * Cn + colBase + tc + jg) =
                make_float4(acc[i][jg], acc[i][jg+1], acc[i][jg+2], acc[i][jg+3]);
        }
    }
}

// ---------------------------------------------------------------------------
extern "C" void kernel_launch(void* const* d_in, const int* in_sizes, int n_in,
                              void* d_out, int out_size)
{
    const float* x     = (const float*)d_in[0];
    const float* Wqkv  = (const float*)d_in[1];
    const float* Wproj = (const float*)d_in[2];
    float* out = (float*)d_out;

    qkv_rope_kernel<<<dim3(NQKV / 128, Mrows / 128), 256>>>(x, Wqkv);

    cudaFuncSetAttribute(attn_kernel, cudaFuncAttributeMaxDynamicSharedMemorySize,
                         2 * Tn * Dn * sizeof(float));
    attn_kernel<<<Bn * Hn, 256, 2 * Tn * Dn * sizeof(float)>>>();

    proj_kernel<<<dim3(Cn / 128, Mrows / 128), 256>>>(Wproj, out);
}

// round 3
// speedup vs baseline: 1.5929x; 1.5929x over previous
#include <cuda_runtime.h>
#include <math.h>

#define Bn   128
#define Tn   256
#define Cn   384
#define Hn   6
#define Dn   64
#define NQKV 1152
#define Mrows (Bn*Tn)   // 32768

// smem layout constants for tf32 GEMM kernels
#define AS_STRIDE 36            // 32 + 4 pad (floats)
#define BS_STRIDE 136           // 128 + 8 pad (floats)
#define AS_SIZE  (128*AS_STRIDE)   // 4608 floats
#define BS_SIZE  (32*BS_STRIDE)    // 4352 floats
#define BUF_SIZE (AS_SIZE + BS_SIZE)  // 8960 floats
#define SMEM_GEMM (2*BUF_SIZE*4)      // 71680 bytes

// Scratch (device globals: allocation-free by rule)
__device__ float g_Q[(size_t)Bn*Hn*Tn*Dn];
__device__ float g_K[(size_t)Bn*Hn*Tn*Dn];
__device__ float g_V[(size_t)Bn*Hn*Tn*Dn];
__device__ float g_O[(size_t)Bn*Hn*Tn*Dn];

__device__ __forceinline__ unsigned f2tf(float f) {
    unsigned u;
    asm("cvt.rna.tf32.f32 %0, %1;" : "=r"(u) : "f"(f));
    return u;
}

__device__ __forceinline__ void mma_tf32(float* c, const unsigned* a, const unsigned* b) {
    asm volatile(
        "mma.sync.aligned.m16n8k8.row.col.f32.tf32.tf32.f32 "
        "{%0,%1,%2,%3}, {%4,%5,%6,%7}, {%8,%9}, {%0,%1,%2,%3};"
        : "+f"(c[0]), "+f"(c[1]), "+f"(c[2]), "+f"(c[3])
        : "r"(a[0]), "r"(a[1]), "r"(a[2]), "r"(a[3]), "r"(b[0]), "r"(b[1]));
}

// ---------------------------------------------------------------------------
// Kernel 1: qkv = x @ W_qkv (tf32 tensor core), fused RoPE, scatter [B,H,T,D].
// CTA tile 128x128, BK=32, 8 warps x (64x32) warp tile, double-buffered smem.
// ---------------------------------------------------------------------------
__global__ __launch_bounds__(256) void qkv_tf32_kernel(
    const float* __restrict__ x, const float* __restrict__ W)
{
    extern __shared__ float sh[];
    const int tid  = threadIdx.x;
    const int lane = tid & 31;
    const int wid  = tid >> 5;
    const int warpM = (wid >> 2) * 64;   // 0 or 64
    const int warpN = (wid & 3) * 32;    // 0..96
    const int rowBase = blockIdx.y * 128;
    const int colBase = blockIdx.x * 128;

    const int arow = tid >> 3;           // 0..31
    const int acol = (tid & 7) * 4;      // 0..28
    const int bk   = tid >> 3;           // 0..31
    const int bcol = (tid & 7) * 4;      // 0..28 (then +32p)

    float4 aReg[4], bReg[4];

    float acc[4][4][4];
    #pragma unroll
    for (int mt = 0; mt < 4; mt++)
        #pragma unroll
        for (int nt = 0; nt < 4; nt++)
            #pragma unroll
            for (int i = 0; i < 4; i++) acc[mt][nt][i] = 0.f;

    // prologue load
    #pragma unroll
    for (int p = 0; p < 4; p++)
        aReg[p] = *(const float4*)(x + (size_t)(rowBase + arow + p*32)*Cn + 0 + acol);
    #pragma unroll
    for (int p = 0; p < 4; p++)
        bReg[p] = *(const float4*)(W + (size_t)(0 + bk)*NQKV + colBase + bcol + p*32);
    {
        float* As = sh;  float* Bs = sh + AS_SIZE;
        #pragma unroll
        for (int p = 0; p < 4; p++)
            *(float4*)(As + (arow + p*32)*AS_STRIDE + acol) = aReg[p];
        #pragma unroll
        for (int p = 0; p < 4; p++)
            *(float4*)(Bs + bk*BS_STRIDE + bcol + p*32) = bReg[p];
    }
    __syncthreads();

    for (int kc = 0; kc < 12; kc++) {
        const int cur = kc & 1;
        if (kc < 11) {
            const int k0 = (kc + 1) * 32;
            #pragma unroll
            for (int p = 0; p < 4; p++)
                aReg[p] = *(const float4*)(x + (size_t)(rowBase + arow + p*32)*Cn + k0 + acol);
            #pragma unroll
            for (int p = 0; p < 4; p++)
                bReg[p] = *(const float4*)(W + (size_t)(k0 + bk)*NQKV + colBase + bcol + p*32);
        }
        const float* As = sh + cur*BUF_SIZE;
        const float* Bs = As + AS_SIZE;
        #pragma unroll
        for (int ks = 0; ks < 4; ks++) {
            const int kb = ks * 8;
            unsigned a[4][4], b[4][2];
            #pragma unroll
            for (int mt = 0; mt < 4; mt++) {
                const int r0 = warpM + mt*16 + (lane >> 2);
                const int c0 = kb + (lane & 3);
                a[mt][0] = f2tf(As[r0*AS_STRIDE + c0]);
                a[mt][1] = f2tf(As[(r0+8)*AS_STRIDE + c0]);
                a[mt][2] = f2tf(As[r0*AS_STRIDE + c0 + 4]);
                a[mt][3] = f2tf(As[(r0+8)*AS_STRIDE + c0 + 4]);
            }
            #pragma unroll
            for (int nt = 0; nt < 4; nt++) {
                const int cn = warpN + nt*8 + (lane >> 2);
                b[nt][0] = f2tf(Bs[(kb + (lane & 3))*BS_STRIDE + cn]);
                b[nt][1] = f2tf(Bs[(kb + 4 + (lane & 3))*BS_STRIDE + cn]);
            }
            #pragma unroll
            for (int mt = 0; mt < 4; mt++)
                #pragma unroll
                for (int nt = 0; nt < 4; nt++)
                    mma_tf32(acc[mt][nt], a[mt], b[nt]);
        }
        if (kc < 11) {
            float* Asw = sh + (cur ^ 1)*BUF_SIZE;
            float* Bsw = Asw + AS_SIZE;
            #pragma unroll
            for (int p = 0; p < 4; p++)
                *(float4*)(Asw + (arow + p*32)*AS_STRIDE + acol) = aReg[p];
            #pragma unroll
            for (int p = 0; p < 4; p++)
                *(float4*)(Bsw + bk*BS_STRIDE + bcol + p*32) = bReg[p];
        }
        __syncthreads();
    }

    // Epilogue: RoPE on q,k; scatter to [B,H,T,D]
    #pragma unroll
    for (int mt = 0; mt < 4; mt++) {
        const int row = rowBase + warpM + mt*16 + (lane >> 2);
        const int bb = row >> 8;
        const int t  = row & 255;
        #pragma unroll
        for (int nt = 0; nt < 4; nt++) {
            const int col = colBase + warpN + nt*8 + (lane & 3)*2;
            const int sel = col / Cn;           // 0=q 1=k 2=v (uniform per CTA)
            const int rem = col - sel * Cn;
            const int h   = rem >> 6;
            const int d   = rem & 63;           // even
            float c0 = acc[mt][nt][0], c1 = acc[mt][nt][1];
            float c2 = acc[mt][nt][2], c3 = acc[mt][nt][3];
            if (sel < 2) {
                const int p = d >> 1;
                const float w = exp2f(-(float)p * 0.41524101186f); // 10000^(-p/32)
                float sn, cs;
                sincosf((float)t * w, &sn, &cs);
                float r0 = c0*cs - c1*sn;
                float r1 = c1*cs + c0*sn;
                c0 = r0; c1 = r1;
                sincosf((float)(t + 8) * w, &sn, &cs);
                float r2 = c2*cs - c3*sn;
                float r3 = c3*cs + c2*sn;
                c2 = r2; c3 = r3;
            }
            float* dst = (sel == 0) ? g_Q : ((sel == 1) ? g_K : g_V);
            size_t i0 = ((((size_t)bb*Hn + h)*Tn + t)*Dn) + d;
            *(float2*)(dst + i0)         = make_float2(c0, c1);
            *(float2*)(dst + i0 + 8*Dn)  = make_float2(c2, c3);
        }
    }
}

// ---------------------------------------------------------------------------
// Kernel 2: causal attention per (b,h). 512 threads, 2 threads per query row
// (each owns 32 of 64 dims). K,V resident in 128KB smem. Online softmax.
// ---------------------------------------------------------------------------
__global__ __launch_bounds__(512) void attn_kernel()
{
    extern __shared__ float sh[];
    float* Ks = sh;
    float* Vs = sh + Tn*Dn;
    const int bh = blockIdx.x;
    const size_t base = (size_t)bh * Tn * Dn;
    const int tid = threadIdx.x;

    const float4* K4 = (const float4*)(g_K + base);
    const float4* V4 = (const float4*)(g_V + base);
    for (int i = tid; i < Tn*Dn/4; i += 512) {
        ((float4*)Ks)[i] = K4[i];
        ((float4*)Vs)[i] = V4[i];
    }
    __syncthreads();

    const int r   = tid >> 1;
    const int off = (tid & 1) * 32;

    float q[32];
    #pragma unroll
    for (int i = 0; i < 8; i++) {
        float4 v = *(const float4*)(g_Q + base + (size_t)r*Dn + off + i*4);
        q[i*4+0] = v.x * 0.125f;   // 1/sqrt(64)
        q[i*4+1] = v.y * 0.125f;
        q[i*4+2] = v.z * 0.125f;
        q[i*4+3] = v.w * 0.125f;
    }

    float m = -INFINITY, l = 0.f;
    float o[32];
    #pragma unroll
    for (int d = 0; d < 32; d++) o[d] = 0.f;

    const int jend = r | 15;       // warp-uniform causal trim
    for (int j = 0; j <= jend; j++) {
        const float* kr = Ks + j*Dn + off;
        float s0 = 0.f, s1 = 0.f, s2 = 0.f, s3 = 0.f;
        #pragma unroll
        for (int d = 0; d < 32; d += 4) {
            s0 = fmaf(q[d+0], kr[d+0], s0);
            s1 = fmaf(q[d+1], kr[d+1], s1);
            s2 = fmaf(q[d+2], kr[d+2], s2);
            s3 = fmaf(q[d+3], kr[d+3], s3);
        }
        float sh_ = (s0 + s1) + (s2 + s3);
        float s = sh_ + __shfl_xor_sync(0xffffffffu, sh_, 1);
        if (j <= r) {
            float mn   = fmaxf(m, s);
            float corr = __expf(m - mn);     // exp(-inf)=0 first iter
            float p    = __expf(s - mn);
            l = l * corr + p;
            const float* vr = Vs + j*Dn + off;
            #pragma unroll
            for (int d = 0; d < 32; d++)
                o[d] = fmaf(o[d], corr, p * vr[d]);
            m = mn;
        }
    }

    const float inv = 1.f / l;
    #pragma unroll
    for (int i = 0; i < 8; i++) {
        float4 v;
        v.x = o[i*4+0] * inv;
        v.y = o[i*4+1] * inv;
        v.z = o[i*4+2] * inv;
        v.w = o[i*4+3] * inv;
        *(float4*)(g_O + base + (size_t)r*Dn + off + i*4) = v;
    }
}

// ---------------------------------------------------------------------------
// Kernel 3: out = attnO @ W_proj (tf32 tensor core). A gathered head-major.
// ---------------------------------------------------------------------------
__global__ __launch_bounds__(256) void proj_tf32_kernel(
    const float* __restrict__ W, float* __restrict__ out)
{
    extern __shared__ float sh[];
    const int tid  = threadIdx.x;
    const int lane = tid & 31;
    const int wid  = tid >> 5;
    const int warpM = (wid >> 2) * 64;
    const int warpN = (wid & 3) * 32;
    const int rowBase = blockIdx.y * 128;
    const int colBase = blockIdx.x * 128;

    const int arow = tid >> 3;
    const int acol = (tid & 7) * 4;
    const int bk   = tid >> 3;
    const int bcol = (tid & 7) * 4;

    float4 aReg[4], bReg[4];

    float acc[4][4][4];
    #pragma unroll
    for (int mt = 0; mt < 4; mt++)
        #pragma unroll
        for (int nt = 0; nt < 4; nt++)
            #pragma unroll
            for (int i = 0; i < 4; i++) acc[mt][nt][i] = 0.f;

    auto loadA = [&](int k0, int p) -> float4 {
        const int gr = rowBase + arow + p*32;
        const int bb = gr >> 8;
        const int t  = gr & 255;
        const int kk = k0 + acol;
        const int h  = kk >> 6;
        const int d  = kk & 63;
        return *(const float4*)(g_O + ((((size_t)bb*Hn + h)*Tn + t)*Dn) + d);
    };

    #pragma unroll
    for (int p = 0; p < 4; p++) aReg[p] = loadA(0, p);
    #pragma unroll
    for (int p = 0; p < 4; p++)
        bReg[p] = *(const float4*)(W + (size_t)(0 + bk)*Cn + colBase + bcol + p*32);
    {
        float* As = sh;  float* Bs = sh + AS_SIZE;
        #pragma unroll
        for (int p = 0; p < 4; p++)
            *(float4*)(As + (arow + p*32)*AS_STRIDE + acol) = aReg[p];
        #pragma unroll
        for (int p = 0; p < 4; p++)
            *(float4*)(Bs + bk*BS_STRIDE + bcol + p*32) = bReg[p];
    }
    __syncthreads();

    for (int kc = 0; kc < 12; kc++) {
        const int cur = kc & 1;
        if (kc < 11) {
            const int k0 = (kc + 1) * 32;
            #pragma unroll
            for (int p = 0; p < 4; p++) aReg[p] = loadA(k0, p);
            #pragma unroll
            for (int p = 0; p < 4; p++)
                bReg[p] = *(const float4*)(W + (size_t)(k0 + bk)*Cn + colBase + bcol + p*32);
        }
        const float* As = sh + cur*BUF_SIZE;
        const float* Bs = As + AS_SIZE;
        #pragma unroll
        for (int ks = 0; ks < 4; ks++) {
            const int kb = ks * 8;
            unsigned a[4][4], b[4][2];
            #pragma unroll
            for (int mt = 0; mt < 4; mt++) {
                const int r0 = warpM + mt*16 + (lane >> 2);
                const int c0 = kb + (lane & 3);
                a[mt][0] = f2tf(As[r0*AS_STRIDE + c0]);
                a[mt][1] = f2tf(As[(r0+8)*AS_STRIDE + c0]);
                a[mt][2] = f2tf(As[r0*AS_STRIDE + c0 + 4]);
                a[mt][3] = f2tf(As[(r0+8)*AS_STRIDE + c0 + 4]);
            }
            #pragma unroll
            for (int nt = 0; nt < 4; nt++) {
                const int cn = warpN + nt*8 + (lane >> 2);
                b[nt][0] = f2tf(Bs[(kb + (lane & 3))*BS_STRIDE + cn]);
                b[nt][1] = f2tf(Bs[(kb + 4 + (lane & 3))*BS_STRIDE + cn]);
            }
            #pragma unroll
            for (int mt = 0; mt < 4; mt++)
                #pragma unroll
                for (int nt = 0; nt < 4; nt++)
                    mma_tf32(acc[mt][nt], a[mt], b[nt]);
        }
        if (kc < 11) {
            float* Asw = sh + (cur ^ 1)*BUF_SIZE;
            float* Bsw = Asw + AS_SIZE;
            #pragma unroll
            for (int p = 0; p < 4; p++)
                *(float4*)(Asw + (arow + p*32)*AS_STRIDE + acol) = aReg[p];
            #pragma unroll
            for (int p = 0; p < 4; p++)
                *(float4*)(Bsw + bk*BS_STRIDE + bcol + p*32) = bReg[p];
        }
        __syncthreads();
    }

    #pragma unroll
    for (int mt = 0; mt < 4; mt++) {
        const int row = rowBase + warpM + mt*16 + (lane >> 2);
        #pragma unroll
        for (int nt = 0; nt < 4; nt++) {
            const int col = colBase + warpN + nt*8 + (lane & 3)*2;
            *(float2*)(out + (size_t)row*Cn + col) =
                make_float2(acc[mt][nt][0], acc[mt][nt][1]);
            *(float2*)(out + (size_t)(row + 8)*Cn + col) =
                make_float2(acc[mt][nt][2], acc[mt][nt][3]);
        }
    }
}

// ---------------------------------------------------------------------------
extern "C" void kernel_launch(void* const* d_in, const int* in_sizes, int n_in,
                              void* d_out, int out_size)
{
    const float* x     = (const float*)d_in[0];
    const float* Wqkv  = (const float*)d_in[1];
    const float* Wproj = (const float*)d_in[2];
    float* out = (float*)d_out;

    cudaFuncSetAttribute(qkv_tf32_kernel,
                         cudaFuncAttributeMaxDynamicSharedMemorySize, SMEM_GEMM);
    cudaFuncSetAttribute(proj_tf32_kernel,
                         cudaFuncAttributeMaxDynamicSharedMemorySize, SMEM_GEMM);
    cudaFuncSetAttribute(attn_kernel,
                         cudaFuncAttributeMaxDynamicSharedMemorySize,
                         2 * Tn * Dn * sizeof(float));

    qkv_tf32_kernel<<<dim3(NQKV/128, Mrows/128), 256, SMEM_GEMM>>>(x, Wqkv);
    attn_kernel<<<Bn*Hn, 512, 2*Tn*Dn*sizeof(float)>>>();
    proj_tf32_kernel<<<dim3(Cn/128, Mrows/128), 256, SMEM_GEMM>>>(Wproj, out);
}

// round 4
// speedup vs baseline: 2.7659x; 1.7364x over previous
#include <cuda_runtime.h>
#include <math.h>

#define Bn   128
#define Tn   256
#define Cn   384
#define Hn   6
#define Dn   64
#define NQKV 1152
#define Mrows (Bn*Tn)   // 32768

// smem layout constants for tf32 GEMM kernels (elements are tf32 bits, unsigned)
#define AS_STRIDE 36            // 32 + 4 pad
#define BS_STRIDE 136           // 128 + 8 pad
#define AS_SIZE  (128*AS_STRIDE)
#define BS_SIZE  (32*BS_STRIDE)
#define BUF_SIZE (AS_SIZE + BS_SIZE)
#define SMEM_GEMM (2*BUF_SIZE*4)      // 71680 bytes

// attention smem strides (in uints)
#define KS_STRIDE 68   // banks for K B-frag: (68j+k)%32 = 4j+k, j0..7 k0..3 -> distinct
#define VS_STRIDE 72   // banks for V B-frag: (72j+n)%32 = 8(j%4)+n -> distinct
#define PS_STRIDE 20   // banks for P A-frag: (20r+k)%32 distinct (verified)
#define SMEM_ATTN ((Tn*KS_STRIDE + Tn*VS_STRIDE + 8*16*PS_STRIDE)*4)  // 153600 B

// Scratch (device globals: allocation-free by rule)
__device__ float g_Q[(size_t)Bn*Hn*Tn*Dn];
__device__ float g_K[(size_t)Bn*Hn*Tn*Dn];
__device__ float g_V[(size_t)Bn*Hn*Tn*Dn];
__device__ float g_O[(size_t)Bn*Hn*Tn*Dn];

__device__ __forceinline__ unsigned f2tf(float f) {
    unsigned u;
    asm("cvt.rna.tf32.f32 %0, %1;" : "=r"(u) : "f"(f));
    return u;
}
__device__ __forceinline__ uint4 tf4(float4 v) {
    return make_uint4(f2tf(v.x), f2tf(v.y), f2tf(v.z), f2tf(v.w));
}

__device__ __forceinline__ void mma_tf32(float* c, const unsigned* a, const unsigned* b) {
    asm volatile(
        "mma.sync.aligned.m16n8k8.row.col.f32.tf32.tf32.f32 "
        "{%0,%1,%2,%3}, {%4,%5,%6,%7}, {%8,%9}, {%0,%1,%2,%3};"
        : "+f"(c[0]), "+f"(c[1]), "+f"(c[2]), "+f"(c[3])
        : "r"(a[0]), "r"(a[1]), "r"(a[2]), "r"(a[3]), "r"(b[0]), "r"(b[1]));
}

// ---------------------------------------------------------------------------
// Kernel 1: qkv = x @ W_qkv (tf32), cvt at smem store, fused RoPE, scatter.
// ---------------------------------------------------------------------------
__global__ __launch_bounds__(256) void qkv_tf32_kernel(
    const float* __restrict__ x, const float* __restrict__ W)
{
    extern __shared__ unsigned shq[];
    const int tid  = threadIdx.x;
    const int lane = tid & 31;
    const int wid  = tid >> 5;
    const int warpM = (wid >> 2) * 64;
    const int warpN = (wid & 3) * 32;
    const int rowBase = blockIdx.y * 128;
    const int colBase = blockIdx.x * 128;

    const int arow = tid >> 3;
    const int acol = (tid & 7) * 4;
    const int bk   = tid >> 3;
    const int bcol = (tid & 7) * 4;

    float4 aReg[4], bReg[4];
    float acc[4][4][4];
    #pragma unroll
    for (int mt = 0; mt < 4; mt++)
        #pragma unroll
        for (int nt = 0; nt < 4; nt++)
            #pragma unroll
            for (int i = 0; i < 4; i++) acc[mt][nt][i] = 0.f;

    #pragma unroll
    for (int p = 0; p < 4; p++)
        aReg[p] = *(const float4*)(x + (size_t)(rowBase + arow + p*32)*Cn + acol);
    #pragma unroll
    for (int p = 0; p < 4; p++)
        bReg[p] = *(const float4*)(W + (size_t)bk*NQKV + colBase + bcol + p*32);
    {
        unsigned* As = shq;  unsigned* Bs = shq + AS_SIZE;
        #pragma unroll
        for (int p = 0; p < 4; p++)
            *(uint4*)(As + (arow + p*32)*AS_STRIDE + acol) = tf4(aReg[p]);
        #pragma unroll
        for (int p = 0; p < 4; p++)
            *(uint4*)(Bs + bk*BS_STRIDE + bcol + p*32) = tf4(bReg[p]);
    }
    __syncthreads();

    for (int kc = 0; kc < 12; kc++) {
        const int cur = kc & 1;
        if (kc < 11) {
            const int k0 = (kc + 1) * 32;
            #pragma unroll
            for (int p = 0; p < 4; p++)
                aReg[p] = *(const float4*)(x + (size_t)(rowBase + arow + p*32)*Cn + k0 + acol);
            #pragma unroll
            for (int p = 0; p < 4; p++)
                bReg[p] = *(const float4*)(W + (size_t)(k0 + bk)*NQKV + colBase + bcol + p*32);
        }
        const unsigned* As = shq + cur*BUF_SIZE;
        const unsigned* Bs = As + AS_SIZE;
        #pragma unroll
        for (int ks = 0; ks < 4; ks++) {
            const int kb = ks * 8;
            unsigned a[4][4], b[4][2];
            #pragma unroll
            for (int mt = 0; mt < 4; mt++) {
                const int r0 = warpM + mt*16 + (lane >> 2);
                const int c0 = kb + (lane & 3);
                a[mt][0] = As[r0*AS_STRIDE + c0];
                a[mt][1] = As[(r0+8)*AS_STRIDE + c0];
                a[mt][2] = As[r0*AS_STRIDE + c0 + 4];
                a[mt][3] = As[(r0+8)*AS_STRIDE + c0 + 4];
            }
            #pragma unroll
            for (int nt = 0; nt < 4; nt++) {
                const int cn = warpN + nt*8 + (lane >> 2);
                b[nt][0] = Bs[(kb + (lane & 3))*BS_STRIDE + cn];
                b[nt][1] = Bs[(kb + 4 + (lane & 3))*BS_STRIDE + cn];
            }
            #pragma unroll
            for (int mt = 0; mt < 4; mt++)
                #pragma unroll
                for (int nt = 0; nt < 4; nt++)
                    mma_tf32(acc[mt][nt], a[mt], b[nt]);
        }
        if (kc < 11) {
            unsigned* Asw = shq + (cur ^ 1)*BUF_SIZE;
            unsigned* Bsw = Asw + AS_SIZE;
            #pragma unroll
            for (int p = 0; p < 4; p++)
                *(uint4*)(Asw + (arow + p*32)*AS_STRIDE + acol) = tf4(aReg[p]);
            #pragma unroll
            for (int p = 0; p < 4; p++)
                *(uint4*)(Bsw + bk*BS_STRIDE + bcol + p*32) = tf4(bReg[p]);
        }
        __syncthreads();
    }

    // Epilogue: RoPE on q,k; scatter to [B,H,T,D]
    #pragma unroll
    for (int mt = 0; mt < 4; mt++) {
        const int row = rowBase + warpM + mt*16 + (lane >> 2);
        const int bb = row >> 8;
        const int t  = row & 255;
        #pragma unroll
        for (int nt = 0; nt < 4; nt++) {
            const int col = colBase + warpN + nt*8 + (lane & 3)*2;
            const int sel = col / Cn;
            const int rem = col - sel * Cn;
            const int h   = rem >> 6;
            const int d   = rem & 63;
            float c0 = acc[mt][nt][0], c1 = acc[mt][nt][1];
            float c2 = acc[mt][nt][2], c3 = acc[mt][nt][3];
            if (sel < 2) {
                const int p = d >> 1;
                const float w = exp2f(-(float)p * 0.41524101186f);
                float sn, cs;
                sincosf((float)t * w, &sn, &cs);
                float r0 = c0*cs - c1*sn;
                float r1 = c1*cs + c0*sn;
                c0 = r0; c1 = r1;
                sincosf((float)(t + 8) * w, &sn, &cs);
                float r2 = c2*cs - c3*sn;
                float r3 = c3*cs + c2*sn;
                c2 = r2; c3 = r3;
            }
            float* dst = (sel == 0) ? g_Q : ((sel == 1) ? g_K : g_V);
            size_t i0 = ((((size_t)bb*Hn + h)*Tn + t)*Dn) + d;
            *(float2*)(dst + i0)         = make_float2(c0, c1);
            *(float2*)(dst + i0 + 8*Dn)  = make_float2(c2, c3);
        }
    }
}

// ---------------------------------------------------------------------------
// Kernel 2: tensor-core flash attention. CTA per (b,h), 8 warps.
// Warp w handles query strips {w, 15-w} (16 rows each) -> 17 key blocks each.
// ---------------------------------------------------------------------------
__global__ __launch_bounds__(256) void attn_mma_kernel()
{
    extern __shared__ unsigned sha[];
    unsigned* Ks = sha;
    unsigned* Vs = sha + Tn*KS_STRIDE;
    unsigned* Ps = Vs  + Tn*VS_STRIDE;

    const int bh = blockIdx.x;
    const size_t base = (size_t)bh * Tn * Dn;
    const int tid = threadIdx.x;
    const int lane = tid & 31;
    const int w = tid >> 5;
    const int qr = lane >> 2;   // 0..7
    const int qk = lane & 3;    // 0..3

    // cvt-copy K, V into smem (tf32 bits)
    for (int i = tid; i < Tn*Dn/4; i += 256) {
        const int row = i >> 4;
        const int col = (i & 15) * 4;
        float4 kv = *(const float4*)(g_K + base + (size_t)row*Dn + col);
        *(uint4*)(Ks + row*KS_STRIDE + col) = tf4(kv);
        float4 vv = *(const float4*)(g_V + base + (size_t)row*Dn + col);
        *(uint4*)(Vs + row*VS_STRIDE + col) = tf4(vv);
    }
    __syncthreads();

    unsigned* Pw = Ps + w * (16*PS_STRIDE);

    #pragma unroll
    for (int si = 0; si < 2; si++) {
        const int strip = si ? (15 - w) : w;
        const int r0 = strip * 16;

        // Q fragments for this strip (scaled by 1/sqrt(64))
        unsigned qf[8][4];
        #pragma unroll
        for (int kc = 0; kc < 8; kc++) {
            const float* qp = g_Q + base + (size_t)(r0 + qr)*Dn + kc*8 + qk;
            qf[kc][0] = f2tf(0.125f * qp[0]);
            qf[kc][1] = f2tf(0.125f * qp[8*Dn]);
            qf[kc][2] = f2tf(0.125f * qp[4]);
            qf[kc][3] = f2tf(0.125f * qp[8*Dn + 4]);
        }

        float o[8][4];
        #pragma unroll
        for (int nt = 0; nt < 8; nt++)
            #pragma unroll
            for (int i = 0; i < 4; i++) o[nt][i] = 0.f;
        float m0 = -INFINITY, m1 = -INFINITY, l0 = 0.f, l1 = 0.f;

        for (int jb = 0; jb <= strip; jb++) {
            const int j0 = jb * 16;
            float s[2][4];
            s[0][0]=s[0][1]=s[0][2]=s[0][3]=0.f;
            s[1][0]=s[1][1]=s[1][2]=s[1][3]=0.f;

            #pragma unroll
            for (int kc = 0; kc < 8; kc++) {
                #pragma unroll
                for (int nt = 0; nt < 2; nt++) {
                    unsigned b[2];
                    const unsigned* kp = Ks + (j0 + nt*8 + qr)*KS_STRIDE + kc*8 + qk;
                    b[0] = kp[0];
                    b[1] = kp[4];
                    mma_tf32(s[nt], qf[kc], b);
                }
            }

            if (jb == strip) {   // diagonal block: mask j > row (local coords)
                #pragma unroll
                for (int nt = 0; nt < 2; nt++) {
                    const int c0 = nt*8 + 2*qk;
                    if (c0     > qr)     s[nt][0] = -INFINITY;
                    if (c0 + 1 > qr)     s[nt][1] = -INFINITY;
                    if (c0     > qr + 8) s[nt][2] = -INFINITY;
                    if (c0 + 1 > qr + 8) s[nt][3] = -INFINITY;
                }
            }

            // row-wise max over quad
            float mx0 = fmaxf(fmaxf(s[0][0], s[0][1]), fmaxf(s[1][0], s[1][1]));
            float mx1 = fmaxf(fmaxf(s[0][2], s[0][3]), fmaxf(s[1][2], s[1][3]));
            mx0 = fmaxf(mx0, __shfl_xor_sync(0xffffffffu, mx0, 1));
            mx0 = fmaxf(mx0, __shfl_xor_sync(0xffffffffu, mx0, 2));
            mx1 = fmaxf(mx1, __shfl_xor_sync(0xffffffffu, mx1, 1));
            mx1 = fmaxf(mx1, __shfl_xor_sync(0xffffffffu, mx1, 2));

            const float mn0 = fmaxf(m0, mx0);
            const float mn1 = fmaxf(m1, mx1);
            const float corr0 = __expf(m0 - mn0);
            const float corr1 = __expf(m1 - mn1);

            float p[2][4];
            #pragma unroll
            for (int nt = 0; nt < 2; nt++) {
                p[nt][0] = __expf(s[nt][0] - mn0);
                p[nt][1] = __expf(s[nt][1] - mn0);
                p[nt][2] = __expf(s[nt][2] - mn1);
                p[nt][3] = __expf(s[nt][3] - mn1);
            }
            float rs0 = p[0][0] + p[0][1] + p[1][0] + p[1][1];
            float rs1 = p[0][2] + p[0][3] + p[1][2] + p[1][3];
            rs0 += __shfl_xor_sync(0xffffffffu, rs0, 1);
            rs0 += __shfl_xor_sync(0xffffffffu, rs0, 2);
            rs1 += __shfl_xor_sync(0xffffffffu, rs1, 1);
            rs1 += __shfl_xor_sync(0xffffffffu, rs1, 2);
            l0 = l0 * corr0 + rs0;
            l1 = l1 * corr1 + rs1;
            m0 = mn0; m1 = mn1;

            #pragma unroll
            for (int nt = 0; nt < 8; nt++) {
                o[nt][0] *= corr0; o[nt][1] *= corr0;
                o[nt][2] *= corr1; o[nt][3] *= corr1;
            }

            // store P (tf32 bits) to per-warp smem buffer
            #pragma unroll
            for (int nt = 0; nt < 2; nt++) {
                *(uint2*)(Pw + qr*PS_STRIDE + nt*8 + 2*qk) =
                    make_uint2(f2tf(p[nt][0]), f2tf(p[nt][1]));
                *(uint2*)(Pw + (qr+8)*PS_STRIDE + nt*8 + 2*qk) =
                    make_uint2(f2tf(p[nt][2]), f2tf(p[nt][3]));
            }
            __syncwarp();

            // O += P @ V
            #pragma unroll
            for (int kc2 = 0; kc2 < 2; kc2++) {
                unsigned pa[4];
                pa[0] = Pw[qr*PS_STRIDE + kc2*8 + qk];
                pa[1] = Pw[(qr+8)*PS_STRIDE + kc2*8 + qk];
                pa[2] = Pw[qr*PS_STRIDE + kc2*8 + qk + 4];
                pa[3] = Pw[(qr+8)*PS_STRIDE + kc2*8 + qk + 4];
                #pragma unroll
                for (int nt = 0; nt < 8; nt++) {
                    unsigned b[2];
                    b[0] = Vs[(j0 + kc2*8 + qk)*VS_STRIDE + nt*8 + qr];
                    b[1] = Vs[(j0 + kc2*8 + 4 + qk)*VS_STRIDE + nt*8 + qr];
                    mma_tf32(o[nt], pa, b);
                }
            }
            __syncwarp();
        }

        const float inv0 = 1.f / l0;
        const float inv1 = 1.f / l1;
        #pragma unroll
        for (int nt = 0; nt < 8; nt++) {
            float* op = g_O + base + (size_t)(r0 + qr)*Dn + nt*8 + 2*qk;
            *(float2*)op            = make_float2(o[nt][0]*inv0, o[nt][1]*inv0);
            *(float2*)(op + 8*Dn)   = make_float2(o[nt][2]*inv1, o[nt][3]*inv1);
        }
    }
}

// ---------------------------------------------------------------------------
// Kernel 3: out = attnO @ W_proj (tf32), cvt at smem store, gathered A.
// ---------------------------------------------------------------------------
__global__ __launch_bounds__(256) void proj_tf32_kernel(
    const float* __restrict__ W, float* __restrict__ out)
{
    extern __shared__ unsigned shp[];
    const int tid  = threadIdx.x;
    const int lane = tid & 31;
    const int wid  = tid >> 5;
    const int warpM = (wid >> 2) * 64;
    const int warpN = (wid & 3) * 32;
    const int rowBase = blockIdx.y * 128;
    const int colBase = blockIdx.x * 128;

    const int arow = tid >> 3;
    const int acol = (tid & 7) * 4;
    const int bk   = tid >> 3;
    const int bcol = (tid & 7) * 4;

    float4 aReg[4], bReg[4];
    float acc[4][4][4];
    #pragma unroll
    for (int mt = 0; mt < 4; mt++)
        #pragma unroll
        for (int nt = 0; nt < 4; nt++)
            #pragma unroll
            for (int i = 0; i < 4; i++) acc[mt][nt][i] = 0.f;

    auto loadA = [&](int k0, int p) -> float4 {
        const int gr = rowBase + arow + p*32;
        const int bb = gr >> 8;
        const int t  = gr & 255;
        const int kk = k0 + acol;
        const int h  = kk >> 6;
        const int d  = kk & 63;
        return *(const float4*)(g_O + ((((size_t)bb*Hn + h)*Tn + t)*Dn) + d);
    };

    #pragma unroll
    for (int p = 0; p < 4; p++) aReg[p] = loadA(0, p);
    #pragma unroll
    for (int p = 0; p < 4; p++)
        bReg[p] = *(const float4*)(W + (size_t)bk*Cn + colBase + bcol + p*32);
    {
        unsigned* As = shp;  unsigned* Bs = shp + AS_SIZE;
        #pragma unroll
        for (int p = 0; p < 4; p++)
            *(uint4*)(As + (arow + p*32)*AS_STRIDE + acol) = tf4(aReg[p]);
        #pragma unroll
        for (int p = 0; p < 4; p++)
            *(uint4*)(Bs + bk*BS_STRIDE + bcol + p*32) = tf4(bReg[p]);
    }
    __syncthreads();

    for (int kc = 0; kc < 12; kc++) {
        const int cur = kc & 1;
        if (kc < 11) {
            const int k0 = (kc + 1) * 32;
            #pragma unroll
            for (int p = 0; p < 4; p++) aReg[p] = loadA(k0, p);
            #pragma unroll
            for (int p = 0; p < 4; p++)
                bReg[p] = *(const float4*)(W + (size_t)(k0 + bk)*Cn + colBase + bcol + p*32);
        }
        const unsigned* As = shp + cur*BUF_SIZE;
        const unsigned* Bs = As + AS_SIZE;
        #pragma unroll
        for (int ks = 0; ks < 4; ks++) {
            const int kb = ks * 8;
            unsigned a[4][4], b[4][2];
            #pragma unroll
            for (int mt = 0; mt < 4; mt++) {
                const int r0 = warpM + mt*16 + (lane >> 2);
                const int c0 = kb + (lane & 3);
                a[mt][0] = As[r0*AS_STRIDE + c0];
                a[mt][1] = As[(r0+8)*AS_STRIDE + c0];
                a[mt][2] = As[r0*AS_STRIDE + c0 + 4];
                a[mt][3] = As[(r0+8)*AS_STRIDE + c0 + 4];
            }
            #pragma unroll
            for (int nt = 0; nt < 4; nt++) {
                const int cn = warpN + nt*8 + (lane >> 2);
                b[nt][0] = Bs[(kb + (lane & 3))*BS_STRIDE + cn];
                b[nt][1] = Bs[(kb + 4 + (lane & 3))*BS_STRIDE + cn];
            }
            #pragma unroll
            for (int mt = 0; mt < 4; mt++)
                #pragma unroll
                for (int nt = 0; nt < 4; nt++)
                    mma_tf32(acc[mt][nt], a[mt], b[nt]);
        }
        if (kc < 11) {
            unsigned* Asw = shp + (cur ^ 1)*BUF_SIZE;
            unsigned* Bsw = Asw + AS_SIZE;
            #pragma unroll
            for (int p = 0; p < 4; p++)
                *(uint4*)(Asw + (arow + p*32)*AS_STRIDE + acol) = tf4(aReg[p]);
            #pragma unroll
            for (int p = 0; p < 4; p++)
                *(uint4*)(Bsw + bk*BS_STRIDE + bcol + p*32) = tf4(bReg[p]);
        }
        __syncthreads();
    }

    #pragma unroll
    for (int mt = 0; mt < 4; mt++) {
        const int row = rowBase + warpM + mt*16 + (lane >> 2);
        #pragma unroll
        for (int nt = 0; nt < 4; nt++) {
            const int col = colBase + warpN + nt*8 + (lane & 3)*2;
            *(float2*)(out + (size_t)row*Cn + col) =
                make_float2(acc[mt][nt][0], acc[mt][nt][1]);
            *(float2*)(out + (size_t)(row + 8)*Cn + col) =
                make_float2(acc[mt][nt][2], acc[mt][nt][3]);
        }
    }
}

// ---------------------------------------------------------------------------
extern "C" void kernel_launch(void* const* d_in, const int* in_sizes, int n_in,
                              void* d_out, int out_size)
{
    const float* x     = (const float*)d_in[0];
    const float* Wqkv  = (const float*)d_in[1];
    const float* Wproj = (const float*)d_in[2];
    float* out = (float*)d_out;

    cudaFuncSetAttribute(qkv_tf32_kernel,
                         cudaFuncAttributeMaxDynamicSharedMemorySize, SMEM_GEMM);
    cudaFuncSetAttribute(proj_tf32_kernel,
                         cudaFuncAttributeMaxDynamicSharedMemorySize, SMEM_GEMM);
    cudaFuncSetAttribute(attn_mma_kernel,
                         cudaFuncAttributeMaxDynamicSharedMemorySize, SMEM_ATTN);

    qkv_tf32_kernel<<<dim3(NQKV/128, Mrows/128), 256, SMEM_GEMM>>>(x, Wqkv);
    attn_mma_kernel<<<Bn*Hn, 256, SMEM_ATTN>>>();
    proj_tf32_kernel<<<dim3(Cn/128, Mrows/128), 256, SMEM_GEMM>>>(Wproj, out);
}